// round 8
// baseline (speedup 1.0000x reference)
#include <cuda_runtime.h>
#include <math.h>

#define B 16
#define LQ 2048
#define EMB1 1024
#define EMB2 768
#define HDIM 1024
#define NHEAD 16
#define DH 64
#define GRIDX 13   // 13*16*2 = 416 blocks <= 444 slots (148 SMs x 3 blocks)

// Scratch (static device globals; no allocation in kernel_launch).
__device__ float g_K[B * HDIM];
__device__ float g_V[B * HDIM];
__device__ float g_Weff[B * NHEAD * EMB1];
__device__ float g_c[B * NHEAD];

// Packed f32x2 FMA: acc = a*b + acc elementwise on (lo,hi) float pairs.
__device__ __forceinline__ void fma2(unsigned long long& acc,
                                     unsigned long long a, unsigned long long b) {
    asm("fma.rn.f32x2 %0, %1, %2, %0;" : "+l"(acc) : "l"(a), "l"(b));
}
__device__ __forceinline__ float unpack_sum(unsigned long long a) {
    float lo, hi;
    asm("mov.b64 {%0, %1}, %2;" : "=f"(lo), "=f"(hi) : "l"(a));
    return lo + hi;
}
// Streaming (evict-first) 128-bit store: keep L2 for emb1 reuse.
__device__ __forceinline__ void stg_cs(float4* p, float4 v) {
    asm volatile("st.global.cs.v4.f32 [%0], {%1, %2, %3, %4};"
                 :: "l"(p), "f"(v.x), "f"(v.y), "f"(v.z), "f"(v.w) : "memory");
}

// ---------------------------------------------------------------------------
// Kernel 1: 256 blocks x 512 thr; block handles 4 consecutive j columns.
// ---------------------------------------------------------------------------
__global__ __launch_bounds__(512, 2) void kv_kernel(const float* __restrict__ emb2,
                          const float* __restrict__ Wk, const float* __restrict__ bk,
                          const float* __restrict__ Wv, const float* __restrict__ bv) {
    __shared__ float4 wk_s[4][EMB2 / 4];   // 12 KB
    __shared__ float4 wv_s[4][EMB2 / 4];   // 12 KB
    int j0 = blockIdx.x * 4;
    int tid = threadIdx.x;

    const float4* Wk4 = (const float4*)(Wk + j0 * EMB2);
    const float4* Wv4 = (const float4*)(Wv + j0 * EMB2);
    for (int t = tid; t < 4 * (EMB2 / 4); t += 512)
        wk_s[t / (EMB2 / 4)][t % (EMB2 / 4)] = __ldg(Wk4 + t);
    for (int t = tid; t < 4 * (EMB2 / 4); t += 512)
        wv_s[t / (EMB2 / 4)][t % (EMB2 / 4)] = __ldg(Wv4 + t);
    __syncthreads();

    int b = tid >> 5, lane = tid & 31;
    const float4* e4 = (const float4*)(emb2 + b * EMB2);

    float4 e[6];
#pragma unroll
    for (int i = 0; i < 6; i++) e[i] = __ldg(&e4[i * 32 + lane]);

    float v[8];                 // v[0..3] = ak[j], v[4..7] = av[j]
#pragma unroll
    for (int jj = 0; jj < 4; jj++) {
        float ak = 0.f, av = 0.f;
#pragma unroll
        for (int i = 0; i < 6; i++) {
            float4 k = wk_s[jj][i * 32 + lane];
            float4 w = wv_s[jj][i * 32 + lane];
            ak = fmaf(e[i].x, k.x, ak); ak = fmaf(e[i].y, k.y, ak);
            ak = fmaf(e[i].z, k.z, ak); ak = fmaf(e[i].w, k.w, ak);
            av = fmaf(e[i].x, w.x, av); av = fmaf(e[i].y, w.y, av);
            av = fmaf(e[i].z, w.z, av); av = fmaf(e[i].w, w.w, av);
        }
        v[jj] = ak; v[jj + 4] = av;
    }

#pragma unroll
    for (int s = 0; s < 3; s++) {
        int o = 1 << s;
        int bit = (lane >> s) & 1;
#pragma unroll
        for (int j = 0; j < (4 >> s); j++) {
            float keep = bit ? v[2 * j + 1] : v[2 * j];
            float send = bit ? v[2 * j] : v[2 * j + 1];
            v[j] = keep + __shfl_xor_sync(0xffffffffu, send, o);
        }
    }
    v[0] += __shfl_xor_sync(0xffffffffu, v[0], 8);
    v[0] += __shfl_xor_sync(0xffffffffu, v[0], 16);

    if (lane < 4)
        g_K[b * HDIM + j0 + lane] = v[0] + bk[j0 + lane];
    else if (lane < 8)
        g_V[b * HDIM + j0 + lane - 4] = v[0] + bv[j0 + lane - 4];
}

// ---------------------------------------------------------------------------
// Kernel 2: Weff[b,h,e] = sum_d Wq[h*64+d, e] * K[b, h*64+d].
// ---------------------------------------------------------------------------
__global__ void weff_kernel(const float* __restrict__ Wq, const float* __restrict__ bq) {
    __shared__ float Wq_s[DH * 128];
    __shared__ float Ks[DH];
    int h = blockIdx.y;
    int e0 = blockIdx.x * 128;
    int bg = blockIdx.z;
    int tid = threadIdx.x;

    if (blockIdx.x == 0 && bg == 0 && tid < B) {
        float a = 0.f;
#pragma unroll 16
        for (int d = 0; d < DH; d++)
            a = fmaf(bq[h * DH + d], g_K[tid * HDIM + h * DH + d], a);
        g_c[tid * NHEAD + h] = a;
    }

#pragma unroll 8
    for (int d = 0; d < DH; d++)
        Wq_s[d * 128 + tid] = Wq[(h * DH + d) * EMB1 + e0 + tid];

    for (int bb = 0; bb < 4; bb++) {
        int b = bg * 4 + bb;
        __syncthreads();
        if (tid < DH) Ks[tid] = g_K[b * HDIM + h * DH + tid];
        __syncthreads();
        float a = 0.f;
#pragma unroll 16
        for (int d = 0; d < DH; d++)
            a = fmaf(Wq_s[d * 128 + tid], Ks[d], a);
        g_Weff[(b * NHEAD + h) * EMB1 + e0 + tid] = a;
    }
}

// ---------------------------------------------------------------------------
// Kernel 3 (main): split-head QUADS. Block (gx, b, hp) handles heads
// hp*8..hp*8+7; warp processes 4 rows per w-fetch (LDS traffic 1/4 of the
// row-pair scheme), single pass (x loaded once per quad -> no L1 thrash).
// 192 thr, (192,3) -> 113 regs for ~96 live (no spills), 3 blocks/SM.
// ---------------------------------------------------------------------------
__global__ __launch_bounds__(192, 3) void main_kernel(const float* __restrict__ emb1,
                                                      float* __restrict__ out) {
    extern __shared__ float sm[];
    float* Weff_s = sm;                    // 8*1024 floats (this head half)
    float* V_s = sm + 8 * EMB1;            // 512 floats
    float* c_s = V_s + 8 * DH;             // 8 floats

    int b = blockIdx.y;
    int hp = blockIdx.z;                   // head half: 0 or 1
    int tid = threadIdx.x;

    // Stage this half's Weff slice, V slice, c slice.
    {
        const float4* Wg = (const float4*)(g_Weff + (size_t)b * NHEAD * EMB1 + hp * 8 * EMB1);
        float4* Ws4 = (float4*)Weff_s;
        for (int t = tid; t < 8 * EMB1 / 4; t += 192)
            Ws4[t] = Wg[t];
        const float4* Vg = (const float4*)(g_V + (size_t)b * HDIM + hp * 8 * DH);
        if (tid < 8 * DH / 4) ((float4*)V_s)[tid] = Vg[tid];
        if (tid < 8) c_s[tid] = g_c[b * NHEAD + hp * 8 + tid];
    }
    __syncthreads();

    int warp = tid >> 5, lane = tid & 31;
    const ulonglong2* Wsd = (const ulonglong2*)Weff_s;
    const float4* Vs4 = (const float4*)V_s;
    int hi = lane >> 4;
    float c_l = c_s[lane & 7];

    // Row quads: 512 per (batch, half) over 13 blocks x 6 warps = 78 warps.
    for (int qd = blockIdx.x * 6 + warp; qd < LQ / 4; qd += GRIDX * 6) {
        const ulonglong2* xb = (const ulonglong2*)(emb1 + ((size_t)b * LQ + qd * 4) * EMB1);

        unsigned long long acc[4][8];
#pragma unroll
        for (int r = 0; r < 4; r++)
#pragma unroll
            for (int h = 0; h < 8; h++) acc[r][h] = 0ull;

        ulonglong2 x[4];
#pragma unroll
        for (int r = 0; r < 4; r++)
            x[r] = __ldg(xb + r * (EMB1 / 4) + lane);

#pragma unroll
        for (int i = 0; i < 8; i++) {
            ulonglong2 xn[4];
            if (i < 7) {                               // prefetch next chunk
#pragma unroll
                for (int r = 0; r < 4; r++)
                    xn[r] = __ldg(xb + r * (EMB1 / 4) + (i + 1) * 32 + lane);
            }
#pragma unroll
            for (int h = 0; h < 8; h++) {
                ulonglong2 w = Wsd[h * 256 + i * 32 + lane];
#pragma unroll
                for (int r = 0; r < 4; r++) {
                    fma2(acc[r][h], x[r].x, w.x);
                    fma2(acc[r][h], x[r].y, w.y);
                }
            }
            if (i < 7) {
#pragma unroll
                for (int r = 0; r < 4; r++) x[r] = xn[r];
            }
        }

        // Per row: fold 8 head-partials so every lane holds head (lane&7).
        float sig[4];
#pragma unroll
        for (int r = 0; r < 4; r++) {
            float v[8];
#pragma unroll
            for (int h = 0; h < 8; h++) v[h] = unpack_sum(acc[r][h]);
#pragma unroll
            for (int s = 0; s < 3; s++) {
                int o = 1 << s;
                int bit = (lane >> s) & 1;
#pragma unroll
                for (int j = 0; j < (4 >> s); j++) {
                    float keep = bit ? v[2 * j + 1] : v[2 * j];
                    float send = bit ? v[2 * j] : v[2 * j + 1];
                    v[j] = keep + __shfl_xor_sync(0xffffffffu, send, o);
                }
            }
            v[0] += __shfl_xor_sync(0xffffffffu, v[0], 8);
            v[0] += __shfl_xor_sync(0xffffffffu, v[0], 16);
            sig[r] = __fdividef(1.f, 1.f + __expf(-(v[0] + c_l)));
        }

        // Store this half of each of the 4 rows (heads hp*8..hp*8+7).
        float4* ob = (float4*)(out + ((size_t)b * LQ + qd * 4) * EMB1) + hp * 128;
#pragma unroll
        for (int i2 = 0; i2 < 4; i2++) {
            // local float4 chunk i2*32+lane -> local head 2*i2 + hi,
            // whose reduced value lives in lane (2*i2 + hi).
            int src = 2 * i2 + hi;
            float4 vv = Vs4[i2 * 32 + lane];
#pragma unroll
            for (int r = 0; r < 4; r++) {
                float s = __shfl_sync(0xffffffffu, sig[r], src);
                float4 o;
                o.x = s * vv.x; o.y = s * vv.y; o.z = s * vv.z; o.w = s * vv.w;
                stg_cs(ob + r * (EMB1 / 4) + i2 * 32 + lane, o);
            }
        }
    }
}

// ---------------------------------------------------------------------------
extern "C" void kernel_launch(void* const* d_in, const int* in_sizes, int n_in,
                              void* d_out, int out_size) {
    const float* emb1 = (const float*)d_in[0];
    const float* emb2 = (const float*)d_in[1];
    const float* Wq   = (const float*)d_in[2];
    const float* bq   = (const float*)d_in[3];
    const float* Wk   = (const float*)d_in[4];
    const float* bk   = (const float*)d_in[5];
    const float* Wv   = (const float*)d_in[6];
    const float* bv   = (const float*)d_in[7];
    float* out = (float*)d_out;

    kv_kernel<<<HDIM / 4, 512>>>(emb2, Wk, bk, Wv, bv);
    weff_kernel<<<dim3(EMB1 / 128, NHEAD, 4), 128>>>(Wq, bq);

    int smem = (8 * EMB1 + 8 * DH + 8) * (int)sizeof(float);   // ~34.9 KB
    static bool attr_set = false;
    if (!attr_set) {
        cudaFuncSetAttribute(main_kernel, cudaFuncAttributeMaxDynamicSharedMemorySize, smem);
        attr_set = true;
    }
    main_kernel<<<dim3(GRIDX, B, 2), 192, smem>>>(emb1, out);
}

// round 9
// speedup vs baseline: 1.0567x; 1.0567x over previous
#include <cuda_runtime.h>
#include <math.h>

#define B 16
#define LQ 2048
#define EMB1 1024
#define EMB2 768
#define HDIM 1024
#define NHEAD 16
#define DH 64
#define GRIDX 18      // 18*16 = 288 blocks = 144 SMs x 2 -> single wave
#define MTHREADS 320  // 10 warps/block, 20 warps/SM at 2 blocks/SM

// Scratch (static device globals; no allocation in kernel_launch).
__device__ float g_K[B * HDIM];
__device__ float g_V[B * HDIM];
__device__ float g_Weff[B * NHEAD * EMB1];
__device__ float g_c[B * NHEAD];

// Packed f32x2 FMA: acc = a*b + acc elementwise on (lo,hi) float pairs.
__device__ __forceinline__ void fma2(unsigned long long& acc,
                                     unsigned long long a, unsigned long long b) {
    asm("fma.rn.f32x2 %0, %1, %2, %0;" : "+l"(acc) : "l"(a), "l"(b));
}
__device__ __forceinline__ float unpack_sum(unsigned long long a) {
    float lo, hi;
    asm("mov.b64 {%0, %1}, %2;" : "=f"(lo), "=f"(hi) : "l"(a));
    return lo + hi;
}

// ---------------------------------------------------------------------------
// Kernel 1: grid (HDIM/4, 2): blockIdx.y selects K or V matrix. 512 thr,
// 4 j-columns staged in 12 KB smem; warp b computes 4 dots + folded reduce.
// ---------------------------------------------------------------------------
__global__ __launch_bounds__(512, 3) void kv_kernel(const float* __restrict__ emb2,
                          const float* __restrict__ Wk, const float* __restrict__ bk,
                          const float* __restrict__ Wv, const float* __restrict__ bv) {
    __shared__ float4 w_s[4][EMB2 / 4];    // 12 KB
    int j0 = blockIdx.x * 4;
    int mat = blockIdx.y;
    int tid = threadIdx.x;

    const float* W = mat ? Wv : Wk;
    const float* bias = mat ? bv : bk;
    float* dst = mat ? g_V : g_K;

    const float4* W4 = (const float4*)(W + j0 * EMB2);
    for (int t = tid; t < 4 * (EMB2 / 4); t += 512)
        w_s[t / (EMB2 / 4)][t % (EMB2 / 4)] = __ldg(W4 + t);
    __syncthreads();

    int b = tid >> 5, lane = tid & 31;
    const float4* e4 = (const float4*)(emb2 + b * EMB2);

    float4 e[6];
#pragma unroll
    for (int i = 0; i < 6; i++) e[i] = __ldg(&e4[i * 32 + lane]);

    float v[4];
#pragma unroll
    for (int jj = 0; jj < 4; jj++) {
        float a = 0.f;
#pragma unroll
        for (int i = 0; i < 6; i++) {
            float4 w = w_s[jj][i * 32 + lane];
            a = fmaf(e[i].x, w.x, a); a = fmaf(e[i].y, w.y, a);
            a = fmaf(e[i].z, w.z, a); a = fmaf(e[i].w, w.w, a);
        }
        v[jj] = a;
    }

    // Fold 4 values -> lane l holds total for j0 + (l & 3).
#pragma unroll
    for (int s = 0; s < 2; s++) {
        int o = 1 << s;
        int bit = (lane >> s) & 1;
#pragma unroll
        for (int j = 0; j < (2 >> s); j++) {
            float keep = bit ? v[2 * j + 1] : v[2 * j];
            float send = bit ? v[2 * j] : v[2 * j + 1];
            v[j] = keep + __shfl_xor_sync(0xffffffffu, send, o);
        }
    }
    v[0] += __shfl_xor_sync(0xffffffffu, v[0], 4);
    v[0] += __shfl_xor_sync(0xffffffffu, v[0], 8);
    v[0] += __shfl_xor_sync(0xffffffffu, v[0], 16);

    if (lane < 4)
        dst[b * HDIM + j0 + lane] = v[0] + bias[j0 + lane];
}

// ---------------------------------------------------------------------------
// Kernel 2: Weff[b,h,e] = sum_d Wq[h*64+d, e] * K[b, h*64+d].
// ---------------------------------------------------------------------------
__global__ void weff_kernel(const float* __restrict__ Wq, const float* __restrict__ bq) {
    __shared__ float Wq_s[DH * 128];
    __shared__ float Ks[DH];
    int h = blockIdx.y;
    int e0 = blockIdx.x * 128;
    int bg = blockIdx.z;
    int tid = threadIdx.x;

    if (blockIdx.x == 0 && bg == 0 && tid < B) {
        float a = 0.f;
#pragma unroll 16
        for (int d = 0; d < DH; d++)
            a = fmaf(bq[h * DH + d], g_K[tid * HDIM + h * DH + d], a);
        g_c[tid * NHEAD + h] = a;
    }

#pragma unroll 8
    for (int d = 0; d < DH; d++)
        Wq_s[d * 128 + tid] = Wq[(h * DH + d) * EMB1 + e0 + tid];

    for (int bb = 0; bb < 4; bb++) {
        int b = bg * 4 + bb;
        __syncthreads();
        if (tid < DH) Ks[tid] = g_K[b * HDIM + h * DH + tid];
        __syncthreads();
        float a = 0.f;
#pragma unroll 16
        for (int d = 0; d < DH; d++)
            a = fmaf(Wq_s[d * 128 + tid], Ks[d], a);
        g_Weff[(b * NHEAD + h) * EMB1 + e0 + tid] = a;
    }
}

// ---------------------------------------------------------------------------
// Kernel 3 (main): R5 row-pair structure, 320 threads (10 warps) -> 20
// warps/SM at 2 blocks/SM. (320,2) = 102 regs for ~75 live: no spills.
// ---------------------------------------------------------------------------
__global__ __launch_bounds__(MTHREADS, 2) void main_kernel(const float* __restrict__ emb1,
                                                           float* __restrict__ out) {
    extern __shared__ float sm[];
    float* Weff_s = sm;                    // 16384 floats
    float* V_s = sm + NHEAD * EMB1;        // 1024 floats
    float* c_s = V_s + HDIM;               // 16 floats

    int b = blockIdx.y;
    int tid = threadIdx.x;

    // Cooperative staging of Weff[b], V[b], c[b]
    {
        const float4* Wg = (const float4*)(g_Weff + (size_t)b * NHEAD * EMB1);
        float4* Ws4 = (float4*)Weff_s;
        for (int i = tid; i < NHEAD * EMB1 / 4; i += MTHREADS)
            Ws4[i] = Wg[i];
        const float4* Vg = (const float4*)(g_V + (size_t)b * HDIM);
        if (tid < HDIM / 4) ((float4*)V_s)[tid] = Vg[tid];
        if (tid < NHEAD) c_s[tid] = g_c[b * NHEAD + tid];
    }
    __syncthreads();

    int warp = tid >> 5, lane = tid & 31;
    const ulonglong2* Wsd = (const ulonglong2*)Weff_s;
    const float4* Vs4 = (const float4*)V_s;
    int hi = lane >> 4;
    float c_l = c_s[lane & 15];

    // Row pairs: 1024 per batch over 18 blocks x 10 warps = 180 warps.
    for (int p = blockIdx.x * 10 + warp; p < LQ / 2; p += GRIDX * 10) {
        const ulonglong2* x0p = (const ulonglong2*)(emb1 + ((size_t)b * LQ + 2 * p) * EMB1);
        const ulonglong2* x1p = x0p + EMB1 / 4;

        ulonglong2 x0 = __ldg(x0p + lane);
        ulonglong2 x1 = __ldg(x1p + lane);

        unsigned long long acc0[NHEAD], acc1[NHEAD];
#pragma unroll
        for (int h = 0; h < NHEAD; h++) { acc0[h] = 0ull; acc1[h] = 0ull; }

#pragma unroll
        for (int i = 0; i < 8; i++) {
            ulonglong2 x0n, x1n;
            if (i < 7) {                               // prefetch next chunk
                x0n = __ldg(x0p + (i + 1) * 32 + lane);
                x1n = __ldg(x1p + (i + 1) * 32 + lane);
            }
#pragma unroll
            for (int h = 0; h < NHEAD; h++) {
                ulonglong2 w = Wsd[h * 256 + i * 32 + lane];
                fma2(acc0[h], x0.x, w.x);
                fma2(acc0[h], x0.y, w.y);
                fma2(acc1[h], x1.x, w.x);
                fma2(acc1[h], x1.y, w.y);
            }
            if (i < 7) { x0 = x0n; x1 = x1n; }
        }

        // Unpack f32x2 partials, then folded reduction: lane l -> head (l&15).
        float v0[NHEAD], v1[NHEAD];
#pragma unroll
        for (int h = 0; h < NHEAD; h++) {
            v0[h] = unpack_sum(acc0[h]);
            v1[h] = unpack_sum(acc1[h]);
        }
#pragma unroll
        for (int s = 0; s < 4; s++) {
            int o = 1 << s;
            int bit = (lane >> s) & 1;
#pragma unroll
            for (int j = 0; j < (8 >> s); j++) {
                float k0 = bit ? v0[2 * j + 1] : v0[2 * j];
                float s0 = bit ? v0[2 * j] : v0[2 * j + 1];
                v0[j] = k0 + __shfl_xor_sync(0xffffffffu, s0, o);
                float k1 = bit ? v1[2 * j + 1] : v1[2 * j];
                float s1 = bit ? v1[2 * j] : v1[2 * j + 1];
                v1[j] = k1 + __shfl_xor_sync(0xffffffffu, s1, o);
            }
        }
        v0[0] += __shfl_xor_sync(0xffffffffu, v0[0], 16);
        v1[0] += __shfl_xor_sync(0xffffffffu, v1[0], 16);

        float sig0 = __fdividef(1.f, 1.f + __expf(-(v0[0] + c_l)));
        float sig1 = __fdividef(1.f, 1.f + __expf(-(v1[0] + c_l)));

        float4* o0 = (float4*)(out + ((size_t)b * LQ + 2 * p) * EMB1);
        float4* o1 = o0 + EMB1 / 4;
#pragma unroll
        for (int i = 0; i < 8; i++) {
            // float4 (i*32+lane) belongs to head 2i + hi; lane (2i+hi) holds it.
            float s0 = __shfl_sync(0xffffffffu, sig0, 2 * i + hi);
            float s1 = __shfl_sync(0xffffffffu, sig1, 2 * i + hi);
            float4 v = Vs4[i * 32 + lane];
            float4 r0, r1;
            r0.x = s0 * v.x; r0.y = s0 * v.y; r0.z = s0 * v.z; r0.w = s0 * v.w;
            r1.x = s1 * v.x; r1.y = s1 * v.y; r1.z = s1 * v.z; r1.w = s1 * v.w;
            o0[i * 32 + lane] = r0;
            o1[i * 32 + lane] = r1;
        }
    }
}

// ---------------------------------------------------------------------------
extern "C" void kernel_launch(void* const* d_in, const int* in_sizes, int n_in,
                              void* d_out, int out_size) {
    const float* emb1 = (const float*)d_in[0];
    const float* emb2 = (const float*)d_in[1];
    const float* Wq   = (const float*)d_in[2];
    const float* bq   = (const float*)d_in[3];
    const float* Wk   = (const float*)d_in[4];
    const float* bk   = (const float*)d_in[5];
    const float* Wv   = (const float*)d_in[6];
    const float* bv   = (const float*)d_in[7];
    float* out = (float*)d_out;

    kv_kernel<<<dim3(HDIM / 4, 2), 512>>>(emb2, Wk, bk, Wv, bv);
    weff_kernel<<<dim3(EMB1 / 128, NHEAD, 4), 128>>>(Wq, bq);

    int smem = (NHEAD * EMB1 + HDIM + NHEAD) * (int)sizeof(float);
    static bool attr_set = false;
    if (!attr_set) {
        cudaFuncSetAttribute(main_kernel, cudaFuncAttributeMaxDynamicSharedMemorySize, smem);
        attr_set = true;
    }
    main_kernel<<<dim3(GRIDX, B), MTHREADS, smem>>>(emb1, out);
}

// round 10
// speedup vs baseline: 1.1101x; 1.0505x over previous
#include <cuda_runtime.h>
#include <math.h>

#define B 16
#define LQ 2048
#define EMB1 1024
#define EMB2 768
#define HDIM 1024
#define NHEAD 16
#define DH 64
#define GRIDX 18      // 18*16 = 288 blocks = 144 SMs x 2 -> single wave

// Scratch (static device globals; no allocation in kernel_launch).
__device__ float g_K[B * HDIM];
__device__ float g_V[B * HDIM];
__device__ float g_Weff[B * NHEAD * EMB1];
__device__ float g_c[B * NHEAD];

// Packed f32x2 FMA: acc = a*b + acc elementwise on (lo,hi) float pairs.
__device__ __forceinline__ void fma2(unsigned long long& acc,
                                     unsigned long long a, unsigned long long b) {
    asm("fma.rn.f32x2 %0, %1, %2, %0;" : "+l"(acc) : "l"(a), "l"(b));
}
__device__ __forceinline__ float unpack_sum(unsigned long long a) {
    float lo, hi;
    asm("mov.b64 {%0, %1}, %2;" : "=f"(lo), "=f"(hi) : "l"(a));
    return lo + hi;
}

// ---------------------------------------------------------------------------
// Kernel 1 (exact R6 version, proven ~10us): 256 blocks x 512 thr; block
// stages 4 j-columns of BOTH Wk and Wv (24 KB); warp b computes 4 K-dots
// and 4 V-dots, folded 8-value reduction.
// ---------------------------------------------------------------------------
__global__ __launch_bounds__(512, 2) void kv_kernel(const float* __restrict__ emb2,
                          const float* __restrict__ Wk, const float* __restrict__ bk,
                          const float* __restrict__ Wv, const float* __restrict__ bv) {
    __shared__ float4 wk_s[4][EMB2 / 4];   // 12 KB
    __shared__ float4 wv_s[4][EMB2 / 4];   // 12 KB
    int j0 = blockIdx.x * 4;
    int tid = threadIdx.x;

    const float4* Wk4 = (const float4*)(Wk + j0 * EMB2);
    const float4* Wv4 = (const float4*)(Wv + j0 * EMB2);
    for (int t = tid; t < 4 * (EMB2 / 4); t += 512)
        wk_s[t / (EMB2 / 4)][t % (EMB2 / 4)] = __ldg(Wk4 + t);
    for (int t = tid; t < 4 * (EMB2 / 4); t += 512)
        wv_s[t / (EMB2 / 4)][t % (EMB2 / 4)] = __ldg(Wv4 + t);
    __syncthreads();

    int b = tid >> 5, lane = tid & 31;
    const float4* e4 = (const float4*)(emb2 + b * EMB2);

    float4 e[6];
#pragma unroll
    for (int i = 0; i < 6; i++) e[i] = __ldg(&e4[i * 32 + lane]);

    float v[8];                 // v[0..3] = ak[j], v[4..7] = av[j]
#pragma unroll
    for (int jj = 0; jj < 4; jj++) {
        float ak = 0.f, av = 0.f;
#pragma unroll
        for (int i = 0; i < 6; i++) {
            float4 k = wk_s[jj][i * 32 + lane];
            float4 w = wv_s[jj][i * 32 + lane];
            ak = fmaf(e[i].x, k.x, ak); ak = fmaf(e[i].y, k.y, ak);
            ak = fmaf(e[i].z, k.z, ak); ak = fmaf(e[i].w, k.w, ak);
            av = fmaf(e[i].x, w.x, av); av = fmaf(e[i].y, w.y, av);
            av = fmaf(e[i].z, w.z, av); av = fmaf(e[i].w, w.w, av);
        }
        v[jj] = ak; v[jj + 4] = av;
    }

#pragma unroll
    for (int s = 0; s < 3; s++) {
        int o = 1 << s;
        int bit = (lane >> s) & 1;
#pragma unroll
        for (int j = 0; j < (4 >> s); j++) {
            float keep = bit ? v[2 * j + 1] : v[2 * j];
            float send = bit ? v[2 * j] : v[2 * j + 1];
            v[j] = keep + __shfl_xor_sync(0xffffffffu, send, o);
        }
    }
    v[0] += __shfl_xor_sync(0xffffffffu, v[0], 8);
    v[0] += __shfl_xor_sync(0xffffffffu, v[0], 16);

    if (lane < 4)
        g_K[b * HDIM + j0 + lane] = v[0] + bk[j0 + lane];
    else if (lane < 8)
        g_V[b * HDIM + j0 + lane - 4] = v[0] + bv[j0 + lane - 4];
}

// ---------------------------------------------------------------------------
// Kernel 2: Weff[b,h,e] = sum_d Wq[h*64+d, e] * K[b, h*64+d].
// ---------------------------------------------------------------------------
__global__ void weff_kernel(const float* __restrict__ Wq, const float* __restrict__ bq) {
    __shared__ float Wq_s[DH * 128];
    __shared__ float Ks[DH];
    int h = blockIdx.y;
    int e0 = blockIdx.x * 128;
    int bg = blockIdx.z;
    int tid = threadIdx.x;

    if (blockIdx.x == 0 && bg == 0 && tid < B) {
        float a = 0.f;
#pragma unroll 16
        for (int d = 0; d < DH; d++)
            a = fmaf(bq[h * DH + d], g_K[tid * HDIM + h * DH + d], a);
        g_c[tid * NHEAD + h] = a;
    }

#pragma unroll 8
    for (int d = 0; d < DH; d++)
        Wq_s[d * 128 + tid] = Wq[(h * DH + d) * EMB1 + e0 + tid];

    for (int bb = 0; bb < 4; bb++) {
        int b = bg * 4 + bb;
        __syncthreads();
        if (tid < DH) Ks[tid] = g_K[b * HDIM + h * DH + tid];
        __syncthreads();
        float a = 0.f;
#pragma unroll 16
        for (int d = 0; d < DH; d++)
            a = fmaf(Wq_s[d * 128 + tid], Ks[d], a);
        g_Weff[(b * NHEAD + h) * EMB1 + e0 + tid] = a;
    }
}

// ---------------------------------------------------------------------------
// Kernel 3 (main): R5 row-pair structure (proven 60us) with prefetch
// DISTANCE 2 on the emb1 stream (triple-buffered x) for deeper MLP on the
// only latency-exposed chain. ~100 live regs < 128 cap at (256,2).
// ---------------------------------------------------------------------------
__global__ __launch_bounds__(256, 2) void main_kernel(const float* __restrict__ emb1,
                                                      float* __restrict__ out) {
    extern __shared__ float sm[];
    float* Weff_s = sm;                    // 16384 floats
    float* V_s = sm + NHEAD * EMB1;        // 1024 floats
    float* c_s = V_s + HDIM;               // 16 floats

    int b = blockIdx.y;
    int tid = threadIdx.x;

    // Cooperative staging of Weff[b], V[b], c[b]
    {
        const float4* Wg = (const float4*)(g_Weff + (size_t)b * NHEAD * EMB1);
        float4* Ws4 = (float4*)Weff_s;
#pragma unroll
        for (int i = 0; i < NHEAD * EMB1 / 4 / 256; i++)
            Ws4[i * 256 + tid] = Wg[i * 256 + tid];
        const float4* Vg = (const float4*)(g_V + (size_t)b * HDIM);
        if (tid < HDIM / 4) ((float4*)V_s)[tid] = Vg[tid];
        if (tid < NHEAD) c_s[tid] = g_c[b * NHEAD + tid];
    }
    __syncthreads();

    int warp = tid >> 5, lane = tid & 31;
    const ulonglong2* Wsd = (const ulonglong2*)Weff_s;
    const float4* Vs4 = (const float4*)V_s;
    int hi = lane >> 4;
    float c_l = c_s[lane & 15];

    // Row pairs: 1024 per batch over 18 blocks x 8 warps = 144 warps.
    for (int p = blockIdx.x * 8 + warp; p < LQ / 2; p += GRIDX * 8) {
        const ulonglong2* x0p = (const ulonglong2*)(emb1 + ((size_t)b * LQ + 2 * p) * EMB1);
        const ulonglong2* x1p = x0p + EMB1 / 4;

        // Triple-buffer: a = current, bch = +1, (loaded in loop) = +2.
        ulonglong2 x0a = __ldg(x0p + lane);
        ulonglong2 x1a = __ldg(x1p + lane);
        ulonglong2 x0b = __ldg(x0p + 32 + lane);
        ulonglong2 x1b = __ldg(x1p + 32 + lane);

        unsigned long long acc0[NHEAD], acc1[NHEAD];
#pragma unroll
        for (int h = 0; h < NHEAD; h++) { acc0[h] = 0ull; acc1[h] = 0ull; }

#pragma unroll
        for (int i = 0; i < 8; i++) {
            ulonglong2 x0c, x1c;
            if (i < 6) {                               // prefetch chunk i+2
                x0c = __ldg(x0p + (i + 2) * 32 + lane);
                x1c = __ldg(x1p + (i + 2) * 32 + lane);
            }
#pragma unroll
            for (int h = 0; h < NHEAD; h++) {
                ulonglong2 w = Wsd[h * 256 + i * 32 + lane];
                fma2(acc0[h], x0a.x, w.x);
                fma2(acc0[h], x0a.y, w.y);
                fma2(acc1[h], x1a.x, w.x);
                fma2(acc1[h], x1a.y, w.y);
            }
            x0a = x0b; x1a = x1b;
            if (i < 6) { x0b = x0c; x1b = x1c; }
        }

        // Unpack f32x2 partials, then folded reduction: lane l -> head (l&15).
        float v0[NHEAD], v1[NHEAD];
#pragma unroll
        for (int h = 0; h < NHEAD; h++) {
            v0[h] = unpack_sum(acc0[h]);
            v1[h] = unpack_sum(acc1[h]);
        }
#pragma unroll
        for (int s = 0; s < 4; s++) {
            int o = 1 << s;
            int bit = (lane >> s) & 1;
#pragma unroll
            for (int j = 0; j < (8 >> s); j++) {
                float k0 = bit ? v0[2 * j + 1] : v0[2 * j];
                float s0 = bit ? v0[2 * j] : v0[2 * j + 1];
                v0[j] = k0 + __shfl_xor_sync(0xffffffffu, s0, o);
                float k1 = bit ? v1[2 * j + 1] : v1[2 * j];
                float s1 = bit ? v1[2 * j] : v1[2 * j + 1];
                v1[j] = k1 + __shfl_xor_sync(0xffffffffu, s1, o);
            }
        }
        v0[0] += __shfl_xor_sync(0xffffffffu, v0[0], 16);
        v1[0] += __shfl_xor_sync(0xffffffffu, v1[0], 16);

        float sig0 = __fdividef(1.f, 1.f + __expf(-(v0[0] + c_l)));
        float sig1 = __fdividef(1.f, 1.f + __expf(-(v1[0] + c_l)));

        float4* o0 = (float4*)(out + ((size_t)b * LQ + 2 * p) * EMB1);
        float4* o1 = o0 + EMB1 / 4;
#pragma unroll
        for (int i = 0; i < 8; i++) {
            // float4 (i*32+lane) belongs to head 2i + hi; lane (2i+hi) holds it.
            float s0 = __shfl_sync(0xffffffffu, sig0, 2 * i + hi);
            float s1 = __shfl_sync(0xffffffffu, sig1, 2 * i + hi);
            float4 v = Vs4[i * 32 + lane];
            float4 r0, r1;
            r0.x = s0 * v.x; r0.y = s0 * v.y; r0.z = s0 * v.z; r0.w = s0 * v.w;
            r1.x = s1 * v.x; r1.y = s1 * v.y; r1.z = s1 * v.z; r1.w = s1 * v.w;
            o0[i * 32 + lane] = r0;
            o1[i * 32 + lane] = r1;
        }
    }
}

// ---------------------------------------------------------------------------
extern "C" void kernel_launch(void* const* d_in, const int* in_sizes, int n_in,
                              void* d_out, int out_size) {
    const float* emb1 = (const float*)d_in[0];
    const float* emb2 = (const float*)d_in[1];
    const float* Wq   = (const float*)d_in[2];
    const float* bq   = (const float*)d_in[3];
    const float* Wk   = (const float*)d_in[4];
    const float* bk   = (const float*)d_in[5];
    const float* Wv   = (const float*)d_in[6];
    const float* bv   = (const float*)d_in[7];
    float* out = (float*)d_out;

    kv_kernel<<<HDIM / 4, 512>>>(emb2, Wk, bk, Wv, bv);
    weff_kernel<<<dim3(EMB1 / 128, NHEAD, 4), 128>>>(Wq, bq);

    int smem = (NHEAD * EMB1 + HDIM + NHEAD) * (int)sizeof(float);
    static bool attr_set = false;
    if (!attr_set) {
        cudaFuncSetAttribute(main_kernel, cudaFuncAttributeMaxDynamicSharedMemorySize, smem);
        attr_set = true;
    }
    main_kernel<<<dim3(GRIDX, B), 256, smem>>>(emb1, out);
}